// round 3
// baseline (speedup 1.0000x reference)
#include <cuda_runtime.h>
#include <cuda_bf16.h>

// Problem dims
#define N_  32
#define C_  64
#define T_  128
#define V_  25
#define F_  204800      // C*T*V
#define H_  256
#define E_  4

// Split-K config for GEMM0
#define S_SPLIT 512
#define FC      400     // F_/S_SPLIT
#define KT      16      // f-tile staged in smem

// Scratch (static device globals — no allocation)
__device__ float g_partials[S_SPLIT * N_ * H_];   // 16 MB
__device__ float g_wgt[N_ * E_];

// ---------------- f32x2 helpers (sm_103a packed fp32 FMA) ----------------
static __device__ __forceinline__ unsigned long long pack2(float lo, float hi) {
    unsigned long long r;
    asm("mov.b64 %0, {%1, %2};" : "=l"(r) : "f"(lo), "f"(hi));
    return r;
}
static __device__ __forceinline__ void unpack2(unsigned long long p, float& lo, float& hi) {
    asm("mov.b64 {%0, %1}, %2;" : "=f"(lo), "=f"(hi) : "l"(p));
}
static __device__ __forceinline__ void ffma2(unsigned long long& acc,
                                             unsigned long long a,
                                             unsigned long long b) {
    asm("fma.rn.f32x2 %0, %1, %2, %0;" : "+l"(acc) : "l"(a), "l"(b));
}

// ---------------- Kernel 1: split-K GEMM0  h0_partial = x @ W0 ----------------
// Grid: S_SPLIT blocks, 128 threads.
// Thread tile: 16 n (as 8 f32x2 pairs) x 4 h. Block covers full 32n x 256h.
__global__ __launch_bounds__(128, 4)
void k1_gemm0(const float* __restrict__ x, const float* __restrict__ W0) {
    __shared__ float x_sh[KT * 32];      // [f_local][n]

    const int tid = threadIdx.x;
    const int pg  = tid >> 6;            // 0..1  -> n-pair group
    const int hg  = tid & 63;            // 0..63 -> h group
    const int h0  = hg << 2;             // 4 h per thread
    const int fbase = blockIdx.x * FC;

    unsigned long long acc[8][4];
#pragma unroll
    for (int i = 0; i < 8; i++)
#pragma unroll
        for (int j = 0; j < 4; j++) acc[i][j] = 0ull;   // two packed 0.0f

    const int ln = tid >> 2;             // 0..31 : n row for x staging
    const int lj = tid & 3;              // 0..3  : f quad

    for (int tile = 0; tile < FC / KT; tile++) {
        const int f0 = fbase + tile * KT;

        // Stage x[:, f0..f0+15] into smem as x_sh[f][n]
        const float4 xv = *(const float4*)(x + (size_t)ln * F_ + f0 + lj * 4);
        x_sh[(lj * 4 + 0) * 32 + ln] = xv.x;
        x_sh[(lj * 4 + 1) * 32 + ln] = xv.y;
        x_sh[(lj * 4 + 2) * 32 + ln] = xv.z;
        x_sh[(lj * 4 + 3) * 32 + ln] = xv.w;
        __syncthreads();

#pragma unroll
        for (int fl = 0; fl < KT; fl++) {
            // W0 row slice for this thread's 4 h columns (coalesced per warp)
            const float4 w4 = *(const float4*)(W0 + (size_t)(f0 + fl) * H_ + h0);
            unsigned long long w2[4];
            w2[0] = pack2(w4.x, w4.x);
            w2[1] = pack2(w4.y, w4.y);
            w2[2] = pack2(w4.z, w4.z);
            w2[3] = pack2(w4.w, w4.w);

            // 8 packed x pairs (broadcast within warp)
            const ulonglong2* xr = (const ulonglong2*)(x_sh + fl * 32 + pg * 16);
            const ulonglong2 q0 = xr[0], q1 = xr[1], q2 = xr[2], q3 = xr[3];
            const unsigned long long xp[8] = {q0.x, q0.y, q1.x, q1.y,
                                              q2.x, q2.y, q3.x, q3.y};
#pragma unroll
            for (int i = 0; i < 8; i++)
#pragma unroll
                for (int j = 0; j < 4; j++)
                    ffma2(acc[i][j], xp[i], w2[j]);
        }
        __syncthreads();
    }

    // Write deterministic partials
    float* outp = g_partials + (size_t)blockIdx.x * (N_ * H_);
#pragma unroll
    for (int i = 0; i < 8; i++) {
        const int n = (pg * 8 + i) * 2;
#pragma unroll
        for (int j = 0; j < 4; j++) {
            float lo, hi;
            unpack2(acc[i][j], lo, hi);
            outp[(n + 0) * H_ + h0 + j] = lo;
            outp[(n + 1) * H_ + h0 + j] = hi;
        }
    }
}

// ---------------- Kernel 2: reduce + MLP + softmax -> g_wgt ----------------
// Grid: 32 blocks (one per n), 256 threads (one per h).
__global__ __launch_bounds__(H_)
void k2_mlp(const float* __restrict__ b0, const float* __restrict__ W1,
            const float* __restrict__ b1, const float* __restrict__ W2,
            const float* __restrict__ b2) {
    __shared__ float sh0[H_];
    __shared__ float sh1[H_];
    __shared__ float lg[E_];

    const int n = blockIdx.x;
    const int h = threadIdx.x;

    // Reduce split-K partials (4-way ILP for MLP)
    float s0 = 0.f, s1 = 0.f, s2 = 0.f, s3 = 0.f;
    const float* p = g_partials + n * H_ + h;
#pragma unroll 4
    for (int q = 0; q < S_SPLIT; q += 4) {
        s0 += p[(size_t)(q + 0) * (N_ * H_)];
        s1 += p[(size_t)(q + 1) * (N_ * H_)];
        s2 += p[(size_t)(q + 2) * (N_ * H_)];
        s3 += p[(size_t)(q + 3) * (N_ * H_)];
    }
    float s = (s0 + s1) + (s2 + s3) + b0[h];
    s = (s > 0.f) ? s : expm1f(s);          // elu
    sh0[h] = s;
    __syncthreads();

    float a = 0.f;
#pragma unroll 8
    for (int k = 0; k < H_; k++) a += sh0[k] * W1[k * H_ + h];
    a += b1[h];
    a = (a > 0.f) ? a : expm1f(a);
    sh1[h] = a;
    __syncthreads();

    if (h < E_) {
        float l = 0.f;
#pragma unroll 8
        for (int k = 0; k < H_; k++) l += sh1[k] * W2[k * E_ + h];
        lg[h] = l + b2[h];
    }
    __syncthreads();

    if (h == 0) {
        const float m = fmaxf(fmaxf(lg[0], lg[1]), fmaxf(lg[2], lg[3]));
        float e[E_];
        float den = 0.f;
#pragma unroll
        for (int ee = 0; ee < E_; ee++) { e[ee] = expf(lg[ee] - m); den += e[ee]; }
        const float inv = 1.f / den;
#pragma unroll
        for (int ee = 0; ee < E_; ee++) g_wgt[n * E_ + ee] = e[ee] * inv;
    }
}

// ---------------- Kernel 3: AS mix + batched graph conv ----------------
// Grid: 32 * 64 blocks (n, t-pair), 160 threads. Each half (80 thr) handles one t.
// Thread tile: 4 c x 5 w.
__global__ __launch_bounds__(160)
void k3_out(const float* __restrict__ x, const float* __restrict__ A,
            float* __restrict__ out) {
    __shared__ float x_sh[2][C_ * 26];   // [t-sel][c*26 + v], padded
    __shared__ float AS_sh[2][640];      // [t-sel][v*25 + w]
    __shared__ float wn[E_];

    const int tid = threadIdx.x;
    const int n   = blockIdx.x >> 6;
    const int tp  = blockIdx.x & 63;

    if (tid < E_) wn[tid] = g_wgt[n * E_ + tid];
    __syncthreads();

    // AS[t][v][w] = sum_e wn[e] * A[e][t][v][w]   (A is L2-resident)
    for (int idx = tid; idx < 2 * 625; idx += 160) {
        const int ts = idx / 625;
        const int vw = idx - ts * 625;
        const int t  = tp * 2 + ts;
        const float* Ab = A + t * 625 + vw;
        AS_sh[ts][vw] = wn[0] * Ab[0]
                      + wn[1] * Ab[1 * T_ * 625]
                      + wn[2] * Ab[2 * T_ * 625]
                      + wn[3] * Ab[3 * T_ * 625];
    }
    // Stage x[n, :, t, :]
    for (int idx = tid; idx < 2 * C_ * V_; idx += 160) {
        const int ts = idx / (C_ * V_);
        const int r  = idx - ts * (C_ * V_);
        const int c  = r / V_;
        const int v  = r - c * V_;
        const int t  = tp * 2 + ts;
        x_sh[ts][c * 26 + v] = x[(size_t)n * F_ + c * (T_ * V_) + t * V_ + v];
    }
    __syncthreads();

    const int ts = tid / 80;
    const int rr = tid - ts * 80;
    const int cg = rr / 5;
    const int wg = rr - cg * 5;
    const int c0 = cg * 4;
    const int w0 = wg * 5;
    const int t  = tp * 2 + ts;

    float acc[4][5];
#pragma unroll
    for (int i = 0; i < 4; i++)
#pragma unroll
        for (int j = 0; j < 5; j++) acc[i][j] = 0.f;

#pragma unroll
    for (int v = 0; v < V_; v++) {
        float xr[4];
#pragma unroll
        for (int i = 0; i < 4; i++) xr[i] = x_sh[ts][(c0 + i) * 26 + v];
        float ar[5];
#pragma unroll
        for (int j = 0; j < 5; j++) ar[j] = AS_sh[ts][v * 25 + w0 + j];
#pragma unroll
        for (int i = 0; i < 4; i++)
#pragma unroll
            for (int j = 0; j < 5; j++) acc[i][j] += xr[i] * ar[j];
    }

#pragma unroll
    for (int i = 0; i < 4; i++)
#pragma unroll
        for (int j = 0; j < 5; j++)
            out[(size_t)n * F_ + (c0 + i) * (T_ * V_) + t * V_ + w0 + j] = acc[i][j];
}

// ---------------- launch ----------------
extern "C" void kernel_launch(void* const* d_in, const int* in_sizes, int n_in,
                              void* d_out, int out_size) {
    (void)in_sizes; (void)n_in; (void)out_size;
    const float* x  = (const float*)d_in[0];
    const float* W0 = (const float*)d_in[1];
    const float* b0 = (const float*)d_in[2];
    const float* W1 = (const float*)d_in[3];
    const float* b1 = (const float*)d_in[4];
    const float* W2 = (const float*)d_in[5];
    const float* b2 = (const float*)d_in[6];
    const float* A  = (const float*)d_in[7];
    float* out = (float*)d_out;

    k1_gemm0<<<S_SPLIT, 128>>>(x, W0);
    k2_mlp<<<N_, H_>>>(b0, W1, b1, W2, b2);
    k3_out<<<N_ * (T_ / 2), 160>>>(x, A, out);
}

// round 6
// speedup vs baseline: 1.7529x; 1.7529x over previous
#include <cuda_runtime.h>
#include <cuda_bf16.h>
#include <cstdint>

// Problem dims
#define N_  32
#define C_  64
#define T_  128
#define V_  25
#define F_  204800      // C*T*V
#define H_  256
#define E_  4

// Split-K config for GEMM0
#define S_SPLIT 512
#define FC      400     // F_/S_SPLIT
#define KT      16      // f-tile staged in smem
#define NTILES  (FC / KT)   // 25

// Scratch (static device globals — no allocation)
__device__ float g_partials[S_SPLIT * N_ * H_];   // 16.7 MB
__device__ float g_h0[N_ * H_];
__device__ float g_wgt[N_ * E_];

// ---------------- f32x2 helpers (sm_103a packed fp32 FMA) ----------------
static __device__ __forceinline__ unsigned long long pack2(float lo, float hi) {
    unsigned long long r;
    asm("mov.b64 %0, {%1, %2};" : "=l"(r) : "f"(lo), "f"(hi));
    return r;
}
static __device__ __forceinline__ void unpack2(unsigned long long p, float& lo, float& hi) {
    asm("mov.b64 {%0, %1}, %2;" : "=f"(lo), "=f"(hi) : "l"(p));
}
static __device__ __forceinline__ void ffma2(unsigned long long& acc,
                                             unsigned long long a,
                                             unsigned long long b) {
    asm("fma.rn.f32x2 %0, %1, %2, %0;" : "+l"(acc) : "l"(a), "l"(b));
}

static __device__ __forceinline__ void cp_async16(unsigned int smem_addr, const void* gptr) {
    asm volatile("cp.async.cg.shared.global [%0], [%1], 16;"
                 :: "r"(smem_addr), "l"(gptr));
}
static __device__ __forceinline__ void cp_commit() {
    asm volatile("cp.async.commit_group;");
}
static __device__ __forceinline__ void cp_wait_all() {
    asm volatile("cp.async.wait_group 0;");
}

// ---------------- Kernel 1: split-K GEMM0 (double-buffered smem pipeline) ----
// Grid: S_SPLIT blocks, 128 threads. Thread tile: 16 n (8 f32x2 pairs) x 4 h.
__global__ __launch_bounds__(128, 4)
void k1_gemm0(const float* __restrict__ x, const float* __restrict__ W0) {
    __shared__ __align__(16) float w_sh[2][KT * H_];   // 2 x 16 KB
    __shared__ __align__(16) float x_sh[2][KT * 32];   // 2 x  2 KB

    const int tid = threadIdx.x;
    const int pg  = tid >> 6;            // 0..1  -> n-pair group
    const int hg  = tid & 63;            // 0..63 -> h group
    const int h0  = hg << 2;             // 4 h per thread
    const int fbase = blockIdx.x * FC;

    const int ln = tid >> 2;             // 0..31 : n row for x staging (8 per warp)
    const int lj = tid & 3;              // 0..3  : f quad

    unsigned long long acc[8][4];
#pragma unroll
    for (int i = 0; i < 8; i++)
#pragma unroll
        for (int j = 0; j < 4; j++) acc[i][j] = 0ull;

    // ---- prologue: stage tile 0 into buffer 0 ----
    {
        const int f0 = fbase;
        // W0 tile: KT*H_ floats = 16384 B = 1024 chunks of 16B; 8 per thread
#pragma unroll
        for (int k = 0; k < 8; k++) {
            const int cid = tid + 128 * k;         // 0..1023
            const int r   = cid >> 6;              // row 0..15
            const int c16 = cid & 63;              // 16B chunk in row
            unsigned int sa = (unsigned int)__cvta_generic_to_shared(
                                  &w_sh[0][r * H_ + c16 * 4]);
            cp_async16(sa, W0 + (size_t)(f0 + r) * H_ + c16 * 4);
        }
        cp_commit();
        const float4 xv = *(const float4*)(x + (size_t)ln * F_ + f0 + lj * 4);
        x_sh[0][(lj * 4 + 0) * 32 + ln] = xv.x;
        x_sh[0][(lj * 4 + 1) * 32 + ln] = xv.y;
        x_sh[0][(lj * 4 + 2) * 32 + ln] = xv.z;
        x_sh[0][(lj * 4 + 3) * 32 + ln] = xv.w;
        cp_wait_all();
    }
    __syncthreads();

    for (int t = 0; t < NTILES; t++) {
        const int buf  = t & 1;
        const int nbuf = buf ^ 1;
        const bool has_next = (t + 1 < NTILES);

        float4 xv;
        if (has_next) {
            const int f1 = fbase + (t + 1) * KT;
            // issue async W0 stage for next tile
#pragma unroll
            for (int k = 0; k < 8; k++) {
                const int cid = tid + 128 * k;
                const int r   = cid >> 6;
                const int c16 = cid & 63;
                unsigned int sa = (unsigned int)__cvta_generic_to_shared(
                                      &w_sh[nbuf][r * H_ + c16 * 4]);
                cp_async16(sa, W0 + (size_t)(f1 + r) * H_ + c16 * 4);
            }
            cp_commit();
            xv = *(const float4*)(x + (size_t)ln * F_ + f1 + lj * 4);
        }

        // ---- compute tile t from smem ----
        const float* wb = &w_sh[buf][0];
        const float* xb = &x_sh[buf][0];
#pragma unroll
        for (int fl = 0; fl < KT; fl++) {
            const float4 w4 = *(const float4*)(wb + fl * H_ + h0);
            unsigned long long w2[4];
            w2[0] = pack2(w4.x, w4.x);
            w2[1] = pack2(w4.y, w4.y);
            w2[2] = pack2(w4.z, w4.z);
            w2[3] = pack2(w4.w, w4.w);

            const ulonglong2* xr = (const ulonglong2*)(xb + fl * 32 + pg * 16);
            const ulonglong2 q0 = xr[0], q1 = xr[1], q2 = xr[2], q3 = xr[3];
            const unsigned long long xp[8] = {q0.x, q0.y, q1.x, q1.y,
                                              q2.x, q2.y, q3.x, q3.y};
#pragma unroll
            for (int i = 0; i < 8; i++)
#pragma unroll
                for (int j = 0; j < 4; j++)
                    ffma2(acc[i][j], xp[i], w2[j]);
        }

        if (has_next) {
            x_sh[nbuf][(lj * 4 + 0) * 32 + ln] = xv.x;
            x_sh[nbuf][(lj * 4 + 1) * 32 + ln] = xv.y;
            x_sh[nbuf][(lj * 4 + 2) * 32 + ln] = xv.z;
            x_sh[nbuf][(lj * 4 + 3) * 32 + ln] = xv.w;
            cp_wait_all();
        }
        __syncthreads();
    }

    // Write deterministic partials
    float* outp = g_partials + (size_t)blockIdx.x * (N_ * H_);
#pragma unroll
    for (int i = 0; i < 8; i++) {
        const int n = (pg * 8 + i) * 2;
#pragma unroll
        for (int j = 0; j < 4; j++) {
            float lo, hi;
            unpack2(acc[i][j], lo, hi);
            outp[(n + 0) * H_ + h0 + j] = lo;
            outp[(n + 1) * H_ + h0 + j] = hi;
        }
    }
}

// ---------------- Kernel 2a: parallel split-K reduce + bias + ELU ----------
// Grid: 256 blocks = (32 n) x (8 h-groups); 256 threads = 32 h x 8 q-chunks.
__global__ __launch_bounds__(256)
void k2a_reduce(const float* __restrict__ b0) {
    __shared__ float red[8][33];

    const int n  = blockIdx.x >> 3;
    const int hq = blockIdx.x & 7;
    const int hl = threadIdx.x & 31;
    const int rg = threadIdx.x >> 5;     // 0..7
    const int h  = hq * 32 + hl;

    float s = 0.f;
    const float* p = g_partials + (size_t)n * H_ + h;
#pragma unroll 8
    for (int q = rg; q < S_SPLIT; q += 8)
        s += p[(size_t)q * (N_ * H_)];

    red[rg][hl] = s;
    __syncthreads();

    if (rg == 0) {
        float v = red[0][hl];
#pragma unroll
        for (int r = 1; r < 8; r++) v += red[r][hl];
        v += b0[h];
        v = (v > 0.f) ? v : expm1f(v);   // ELU
        g_h0[n * H_ + h] = v;
    }
}

// ---------------- Kernel 2b: MLP layers 2/3 + softmax -> g_wgt -------------
// Grid: 32 blocks (one per n), 256 threads (one per h).
__global__ __launch_bounds__(H_)
void k2b_mlp(const float* __restrict__ W1, const float* __restrict__ b1,
             const float* __restrict__ W2, const float* __restrict__ b2) {
    __shared__ float sh0[H_];
    __shared__ float sh1[H_];
    __shared__ float lg[E_];

    const int n = blockIdx.x;
    const int h = threadIdx.x;

    sh0[h] = g_h0[n * H_ + h];
    __syncthreads();

    float a = 0.f;
#pragma unroll 8
    for (int k = 0; k < H_; k++) a += sh0[k] * W1[k * H_ + h];
    a += b1[h];
    a = (a > 0.f) ? a : expm1f(a);
    sh1[h] = a;
    __syncthreads();

    if (h < E_) {
        float l = 0.f;
#pragma unroll 8
        for (int k = 0; k < H_; k++) l += sh1[k] * W2[k * E_ + h];
        lg[h] = l + b2[h];
    }
    __syncthreads();

    if (h == 0) {
        const float m = fmaxf(fmaxf(lg[0], lg[1]), fmaxf(lg[2], lg[3]));
        float e[E_];
        float den = 0.f;
#pragma unroll
        for (int ee = 0; ee < E_; ee++) { e[ee] = expf(lg[ee] - m); den += e[ee]; }
        const float inv = 1.f / den;
#pragma unroll
        for (int ee = 0; ee < E_; ee++) g_wgt[n * E_ + ee] = e[ee] * inv;
    }
}

// ---------------- Kernel 3: AS mix + batched graph conv --------------------
// Grid: 32 n x 32 t-quads = 1024 blocks, 256 threads.
// Thread (t = tid>>6, c = tid&63) computes out[n, c, t, 0..24].
#define K3_XPAD 26
#define K3_APAD 28
__global__ __launch_bounds__(256)
void k3_out(const float* __restrict__ x, const float* __restrict__ A,
            float* __restrict__ out) {
    __shared__ __align__(16) float x_sh[4 * C_ * K3_XPAD];   // 26.6 KB (reused for out)
    __shared__ __align__(16) float AS_sh[4 * V_ * K3_APAD];  // 11.2 KB
    __shared__ float wn[E_];

    const int tid = threadIdx.x;
    const int n   = blockIdx.x >> 5;
    const int tq  = blockIdx.x & 31;
    const int t0  = tq * 4;

    if (tid < E_) wn[tid] = g_wgt[n * E_ + tid];
    __syncthreads();

    // AS[t][v][w] = sum_e wn[e] * A[e][t0+t][v][w]
    for (int idx = tid; idx < 4 * V_ * V_; idx += 256) {
        const int tt = idx / (V_ * V_);
        const int r  = idx - tt * (V_ * V_);
        const int v  = r / V_;
        const int w  = r - v * V_;
        const float* Ab = A + (size_t)(t0 + tt) * (V_ * V_) + r;
        AS_sh[tt * (V_ * K3_APAD) + v * K3_APAD + w] =
              wn[0] * Ab[0]
            + wn[1] * Ab[1 * T_ * V_ * V_]
            + wn[2] * Ab[2 * T_ * V_ * V_]
            + wn[3] * Ab[3 * T_ * V_ * V_];
    }

    // Stage x[n, :, t0:t0+4, :] — 100 contiguous floats per c, float4 loads
    for (int q = tid; q < C_ * 25; q += 256) {           // 1600 float4
        const int c = q / 25;
        const int r = q - c * 25;
        const float4 xv = *(const float4*)(x + (size_t)n * F_ + c * (T_ * V_)
                                             + t0 * V_ + r * 4);
        const int m0 = r * 4;
#pragma unroll
        for (int s = 0; s < 4; s++) {
            const int m  = m0 + s;
            const int tt = m / 25;
            const int v  = m - tt * 25;
            const float val = (s == 0) ? xv.x : (s == 1) ? xv.y : (s == 2) ? xv.z : xv.w;
            x_sh[tt * (C_ * K3_XPAD) + c * K3_XPAD + v] = val;
        }
    }
    __syncthreads();

    const int tt = tid >> 6;             // warp-uniform (broadcast AS reads)
    const int c  = tid & 63;

    unsigned long long acc2[12];
#pragma unroll
    for (int j = 0; j < 12; j++) acc2[j] = 0ull;
    float acc1 = 0.f;

    const float* xrow = x_sh + tt * (C_ * K3_XPAD) + c * K3_XPAD;
    const float* asb  = AS_sh + tt * (V_ * K3_APAD);
#pragma unroll
    for (int v = 0; v < V_; v++) {
        const float xv = xrow[v];
        const unsigned long long xx = pack2(xv, xv);
        const unsigned long long* arow =
            (const unsigned long long*)(asb + v * K3_APAD);
#pragma unroll
        for (int j = 0; j < 12; j++) ffma2(acc2[j], xx, arow[j]);
        acc1 += xv * ((const float*)arow)[24];
    }

    __syncthreads();   // done reading x_sh — reuse as out staging

    float* osh = x_sh;                   // [c][100] layout
    float* orow = osh + c * 100 + tt * 25;
#pragma unroll
    for (int j = 0; j < 12; j++) {
        float lo, hi;
        unpack2(acc2[j], lo, hi);
        orow[2 * j + 0] = lo;
        orow[2 * j + 1] = hi;
    }
    orow[24] = acc1;
    __syncthreads();

    // Coalesced float4 copy-out: per c, 100 contiguous floats in gmem
    for (int q = tid; q < C_ * 25; q += 256) {
        const int c2 = q / 25;
        const int m  = q - c2 * 25;
        const float4 v4 = *(const float4*)(osh + c2 * 100 + m * 4);
        *(float4*)(out + (size_t)n * F_ + c2 * (T_ * V_) + t0 * V_ + m * 4) = v4;
    }
}

// ---------------- launch ----------------
extern "C" void kernel_launch(void* const* d_in, const int* in_sizes, int n_in,
                              void* d_out, int out_size) {
    (void)in_sizes; (void)n_in; (void)out_size;
    const float* x  = (const float*)d_in[0];
    const float* W0 = (const float*)d_in[1];
    const float* b0 = (const float*)d_in[2];
    const float* W1 = (const float*)d_in[3];
    const float* b1 = (const float*)d_in[4];
    const float* W2 = (const float*)d_in[5];
    const float* b2 = (const float*)d_in[6];
    const float* A  = (const float*)d_in[7];
    float* out = (float*)d_out;

    k1_gemm0<<<S_SPLIT, 128>>>(x, W0);
    k2a_reduce<<<256, 256>>>(b0);
    k2b_mlp<<<N_, H_>>>(W1, b1, W2, b2);
    k3_out<<<N_ * (T_ / 4), 256>>>(x, A, out);
}